// round 15
// baseline (speedup 1.0000x reference)
#include <cuda_runtime.h>
#include <cuda_bf16.h>
#include <math.h>
#include <stdint.h>

#define BB 2
#define SS 2048
#define DM 1024
#define HH 16
#define DKK 64
#define HDK 1024
#define UU 40
#define SKK 40
#define NR (BB*SS)
#define BH (BB*HH)
#define NCH 16

// ---------------- device scratch ----------------
__device__ __align__(256) float g_q[(size_t)BH*SS*DKK];
__device__ __align__(256) float g_k[(size_t)BH*SS*DKK];
__device__ __align__(256) float g_v[(size_t)BH*SS*DKK];
__device__ __align__(256) float g_m[(size_t)BH*SS];
__device__ int   g_top[BH*UU];
__device__ __align__(256) float g_vmean[BH*DKK];
__device__ __align__(256) float g_vpart[BH*NCH*DKK];
__device__ __align__(256) float g_delta[BH*UU*DKK];
__device__ __align__(256) float g_base[BB*DM];
__device__ __align__(256) float g_pre[(size_t)NR*DM];
// packed bf16 planes
__device__ __align__(256) char g_pa0[10485760];
__device__ __align__(256) char g_pa1[10485760];
__device__ __align__(256) char g_pb0[7864320];
__device__ __align__(256) char g_pb1[7864320];
__device__ __align__(256) float g_pmax[BH*NCH*UU];
__device__ __align__(256) float g_psum[BH*NCH*UU];
__device__ __align__(256) float g_po[(size_t)BH*NCH*UU*DKK];

// ---------------- helpers ----------------
__device__ __forceinline__ uint32_t smem_u32(const void* p) {
    uint32_t a;
    asm("{ .reg .u64 t; cvta.to.shared.u64 t, %1; cvt.u32.u64 %0, t; }" : "=r"(a) : "l"(p));
    return a;
}
#define MB_INIT(mb, c)   asm volatile("mbarrier.init.shared.b64 [%0], %1;" :: "r"((uint32_t)(mb)), "r"((uint32_t)(c)) : "memory")
#define MB_EXPECT(mb, bytes) asm volatile("mbarrier.arrive.expect_tx.shared.b64 _, [%0], %1;" :: "r"((uint32_t)(mb)), "r"((uint32_t)(bytes)) : "memory")
#define MB_WAIT(mb, pa) do { \
    uint32_t _m = (uint32_t)(mb), _p = (uint32_t)(pa), _d; \
    asm volatile("{ .reg .pred p; mbarrier.try_wait.parity.acquire.cta.shared::cta.b64 p, [%1], %2; selp.b32 %0, 1, 0, p; }" : "=r"(_d) : "r"(_m), "r"(_p) : "memory"); \
    if (!_d) { asm volatile("{ .reg .pred P1;\nWL_%=: mbarrier.try_wait.parity.acquire.cta.shared::cta.b64 P1, [%0], %1, 0x989680;\n @P1 bra.uni WD_%=;\n bra.uni WL_%=;\nWD_%=: }" :: "r"(_m), "r"(_p) : "memory"); } } while (0)
#define BULK_G2S(dst, src, bytes, mb) \
    asm volatile("cp.async.bulk.shared::cluster.global.mbarrier::complete_tx::bytes [%0], [%1], %2, [%3];" \
        :: "r"((uint32_t)(dst)), "l"(src), "r"((uint32_t)(bytes)), "r"((uint32_t)(mb)) : "memory")
#define LDSM4(r0,r1,r2,r3,addr) \
    asm volatile("ldmatrix.sync.aligned.m8n8.x4.shared.b16 {%0,%1,%2,%3}, [%4];" \
        : "=r"(r0), "=r"(r1), "=r"(r2), "=r"(r3) : "r"(addr))
#define MMA16816(d0,d1,d2,d3,a0,a1,a2,a3,b0,b1) \
    asm volatile("mma.sync.aligned.m16n8k16.row.col.f32.bf16.bf16.f32 " \
        "{%0,%1,%2,%3}, {%4,%5,%6,%7}, {%8,%9}, {%0,%1,%2,%3};" \
        : "+f"(d0), "+f"(d1), "+f"(d2), "+f"(d3) \
        : "r"(a0), "r"(a1), "r"(a2), "r"(a3), "r"(b0), "r"(b1))

#define RSTR 80
#define AP 10240
#define BPQ 10240
#define STG (2*AP + 2*BPQ)
#define NSTG 2
#define QSMEM (NSTG*STG)
#define NCHK 32

// ---------------- 0a) split hidden_states -> packed 2-plane bf16 ---------
__global__ void split2_hs(const float* __restrict__ hs)
{
    size_t i = (size_t)blockIdx.x * 256 + threadIdx.x;
    int row = (int)(i >> 9);
    int k = (int)(i & 511) * 2;
    float2 x = ((const float2*)hs)[i];
    __nv_bfloat16 h0 = __float2bfloat16(x.x), h1 = __float2bfloat16(x.y);
    __nv_bfloat16 l0 = __float2bfloat16(x.x - __bfloat162float(h0));
    __nv_bfloat16 l1 = __float2bfloat16(x.y - __bfloat162float(h1));
    size_t off = ((size_t)((row >> 7) * 32 + (k >> 5))) * AP + (row & 127) * RSTR + (k & 31) * 2;
    *(__nv_bfloat162*)(g_pa0 + off) = __halves2bfloat162(h0, h1);
    *(__nv_bfloat162*)(g_pa1 + off) = __halves2bfloat162(l0, l1);
}

// ---------------- 0b) transpose W -> packed [n][k] 2-plane ---------------
__global__ void wtrans2(const float* __restrict__ wq, const float* __restrict__ wk,
                        const float* __restrict__ wv)
{
    int z = blockIdx.z;
    const float* __restrict__ W = (z == 0) ? wq : (z == 1) ? wk : wv;
    const float wsc = (z == 0) ? 0.125f : 1.0f;
    __shared__ float tile[32][33];
    int n0 = blockIdx.x * 32, k0 = blockIdx.y * 32;
    int tx = threadIdx.x, ty = threadIdx.y;
    #pragma unroll
    for (int i = 0; i < 4; i++)
        tile[ty + i*8][tx] = W[(size_t)(k0 + ty + i*8) * HDK + n0 + tx] * wsc;
    __syncthreads();
    #pragma unroll
    for (int i = 0; i < 4; i++) {
        float x = tile[tx][ty + i*8];
        __nv_bfloat16 h = __float2bfloat16(x);
        __nv_bfloat16 l = __float2bfloat16(x - __bfloat162float(h));
        int n = n0 + ty + i*8, k = k0 + tx;
        size_t off = (((size_t)(z * 8) + (n >> 7)) * 32 + (k >> 5)) * BPQ + (n & 127) * RSTR + (k & 31) * 2;
        *(__nv_bfloat16*)(g_pb0 + off) = h;
        *(__nv_bfloat16*)(g_pb1 + off) = l;
    }
}

// ---------------- shared tile body (R10-proven 128x128, 2 CTAs/SM) -------
__device__ __forceinline__ void qkv_tile(uint32_t sb, uint32_t mb0, int which, int rb, int nb)
{
    const int t = threadIdx.x, warp = t >> 5, lane = t & 31;
    const int row0 = rb * 128, n0 = nb * 128;
    const int wm = (warp >> 2) * 32, wn = (warp & 3) * 32;
    const int mi = lane >> 3, r8 = lane & 7;

    if (t == 0) { MB_INIT(mb0, 1); MB_INIT(mb0 + 8, 1); }
    __syncthreads();

    const char* sA0 = g_pa0 + (size_t)rb * 32 * AP;
    const char* sA1 = g_pa1 + (size_t)rb * 32 * AP;
    const char* sB0 = g_pb0 + (size_t)(which * 8 + nb) * 32 * BPQ;
    const char* sB1 = g_pb1 + (size_t)(which * 8 + nb) * 32 * BPQ;

    if (t == 0) {
        #pragma unroll
        for (int c = 0; c < NSTG; c++) {
            uint32_t mb = mb0 + c * 8;
            uint32_t dst = sb + c * STG;
            MB_EXPECT(mb, STG);
            BULK_G2S(dst,             sA0 + (size_t)c * AP,  AP,  mb);
            BULK_G2S(dst + AP,        sA1 + (size_t)c * AP,  AP,  mb);
            BULK_G2S(dst + 2*AP,      sB0 + (size_t)c * BPQ, BPQ, mb);
            BULK_G2S(dst + 2*AP+BPQ,  sB1 + (size_t)c * BPQ, BPQ, mb);
        }
    }

    float acc[2][4][4];
    #pragma unroll
    for (int i = 0; i < 2; i++)
        #pragma unroll
        for (int j = 0; j < 4; j++) {
            acc[i][j][0] = 0.f; acc[i][j][1] = 0.f; acc[i][j][2] = 0.f; acc[i][j][3] = 0.f;
        }

    for (int c = 0; c < NCHK; c++) {
        int s = c & 1;
        MB_WAIT(mb0 + s * 8, (c >> 1) & 1);

        uint32_t stA = sb + s * STG;
        uint32_t stB = stA + 2 * AP;

        #pragma unroll
        for (int si = 0; si < 2; si++) {
            uint32_t aoff = (uint32_t)((wm + (mi & 1) * 8 + r8) * RSTR + (si * 16 + (mi >> 1) * 8) * 2);
            uint32_t boff = (uint32_t)((wn + (mi >> 1) * 8 + r8) * RSTR + (si * 16 + (mi & 1) * 8) * 2);

            uint32_t a[2][4], bf[4][2];
            #pragma unroll
            for (int nt2 = 0; nt2 < 2; nt2++) {
                uint32_t ad = stB + boff + nt2 * 16 * RSTR;
                LDSM4(bf[nt2*2][0], bf[nt2*2][1], bf[nt2*2+1][0], bf[nt2*2+1][1], ad);
            }
            #pragma unroll
            for (int mt = 0; mt < 2; mt++) {
                uint32_t ad = stA + aoff + mt * 16 * RSTR;
                LDSM4(a[mt][0], a[mt][1], a[mt][2], a[mt][3], ad);
            }
            #pragma unroll
            for (int mt = 0; mt < 2; mt++)
                #pragma unroll
                for (int nt = 0; nt < 4; nt++)
                    MMA16816(acc[mt][nt][0], acc[mt][nt][1], acc[mt][nt][2], acc[mt][nt][3],
                             a[mt][0], a[mt][1], a[mt][2], a[mt][3], bf[nt][0], bf[nt][1]);
            #pragma unroll
            for (int mt = 0; mt < 2; mt++) {
                uint32_t ad = stA + AP + aoff + mt * 16 * RSTR;
                LDSM4(a[mt][0], a[mt][1], a[mt][2], a[mt][3], ad);
            }
            #pragma unroll
            for (int mt = 0; mt < 2; mt++)
                #pragma unroll
                for (int nt = 0; nt < 4; nt++)
                    MMA16816(acc[mt][nt][0], acc[mt][nt][1], acc[mt][nt][2], acc[mt][nt][3],
                             a[mt][0], a[mt][1], a[mt][2], a[mt][3], bf[nt][0], bf[nt][1]);
            #pragma unroll
            for (int nt2 = 0; nt2 < 2; nt2++) {
                uint32_t ad = stB + BPQ + boff + nt2 * 16 * RSTR;
                LDSM4(bf[nt2*2][0], bf[nt2*2][1], bf[nt2*2+1][0], bf[nt2*2+1][1], ad);
            }
            #pragma unroll
            for (int mt = 0; mt < 2; mt++) {
                uint32_t ad = stA + aoff + mt * 16 * RSTR;
                LDSM4(a[mt][0], a[mt][1], a[mt][2], a[mt][3], ad);
            }
            #pragma unroll
            for (int mt = 0; mt < 2; mt++)
                #pragma unroll
                for (int nt = 0; nt < 4; nt++)
                    MMA16816(acc[mt][nt][0], acc[mt][nt][1], acc[mt][nt][2], acc[mt][nt][3],
                             a[mt][0], a[mt][1], a[mt][2], a[mt][3], bf[nt][0], bf[nt][1]);
        }
        __syncthreads();
        if (t == 0 && c + NSTG < NCHK) {
            int cn = c + NSTG;
            uint32_t mb = mb0 + s * 8;
            uint32_t dst = sb + s * STG;
            MB_EXPECT(mb, STG);
            BULK_G2S(dst,            sA0 + (size_t)cn * AP,  AP,  mb);
            BULK_G2S(dst + AP,       sA1 + (size_t)cn * AP,  AP,  mb);
            BULK_G2S(dst + 2*AP,     sB0 + (size_t)cn * BPQ, BPQ, mb);
            BULK_G2S(dst + 2*AP+BPQ, sB1 + (size_t)cn * BPQ, BPQ, mb);
        }
    }

    float* __restrict__ O = (which == 0) ? g_q : (which == 1) ? g_k : g_v;
    const int gid = lane >> 2, tig = lane & 3;
    #pragma unroll
    for (int mt = 0; mt < 2; mt++) {
        int row = row0 + wm + mt * 16 + gid;
        int b = row >> 11, s = row & (SS - 1);
        int b8 = (row + 8) >> 11, s8 = (row + 8) & (SS - 1);
        #pragma unroll
        for (int nt = 0; nt < 4; nt++) {
            int col = n0 + wn + nt * 8 + tig * 2;
            int h = col >> 6, d0c = col & 63;
            float2 v0 = make_float2(acc[mt][nt][0], acc[mt][nt][1]);
            float2 v1 = make_float2(acc[mt][nt][2], acc[mt][nt][3]);
            *(float2*)&O[(((size_t)(b  * HH + h)) * SS + s ) * DKK + d0c] = v0;
            *(float2*)&O[(((size_t)(b8 * HH + h)) * SS + s8) * DKK + d0c] = v1;
        }
    }
}

// ---------------- 1) combined qkv GEMM (768 blocks, tight wave pack) -----
__global__ void __launch_bounds__(512, 2) qkv_mma()
{
    extern __shared__ char smem[];
    __shared__ uint64_t mbars[NSTG];
    qkv_tile(smem_u32(smem), smem_u32(&mbars[0]), blockIdx.z, blockIdx.y, blockIdx.x);
}

// ---------------- 2) sampled scores: low-wavefront layout ----------------
// 8 lanes per j, 4 j per warp-instr: 2 wavefronts per j
__global__ void __launch_bounds__(512) sample_m_kernel(const int* __restrict__ idx)
{
    const int sblk = blockIdx.x;
    const int bh = sblk >> 7;
    const int l = ((sblk & 127) << 4) + (threadIdx.x >> 5);
    const int lane = threadIdx.x & 31;
    const int jg = lane >> 3;
    const int sl = lane & 7;
    const float4* qr = (const float4*)(g_q + ((size_t)bh * SS + l) * DKK);
    float4 qa = qr[sl], qb = qr[sl + 8];
    const float* __restrict__ kbase = g_k + (size_t)bh * SS * DKK;
    const int* __restrict__ ip = idx + l * SKK;
    float mx = -3.4e38f, sm = 0.f;
    #pragma unroll
    for (int jt = 0; jt < SKK; jt += 4) {
        int kk = ip[jt + jg];
        const float4* kr = (const float4*)(kbase + (size_t)kk * DKK);
        float4 ka = kr[sl], kb = kr[sl + 8];
        float p = qa.x*ka.x + qa.y*ka.y + qa.z*ka.z + qa.w*ka.w
                + qb.x*kb.x + qb.y*kb.y + qb.z*kb.z + qb.w*kb.w;
        p += __shfl_xor_sync(0xffffffffu, p, 1);
        p += __shfl_xor_sync(0xffffffffu, p, 2);
        p += __shfl_xor_sync(0xffffffffu, p, 4);
        mx = fmaxf(mx, p);
        sm += p;
    }
    #pragma unroll
    for (int o = 8; o < 32; o <<= 1) {
        mx = fmaxf(mx, __shfl_xor_sync(0xffffffffu, mx, o));
        sm += __shfl_xor_sync(0xffffffffu, sm, o);
    }
    if (lane == 0) g_m[(size_t)bh * SS + l] = mx - sm * (1.0f / (float)SS);
}

// ---------------- 3) top-40 ----------------------------------------------
__global__ void __launch_bounds__(1024) topk_kernel()
{
    const int bh = blockIdx.x, t = threadIdx.x;
    const int lane = t & 31, wid = t >> 5;
    __shared__ float wv[32];
    __shared__ int   wi[32];
    __shared__ int   winner;
    float v0 = g_m[(size_t)bh * SS + t];
    float v1 = g_m[(size_t)bh * SS + t + 1024];

    for (int it = 0; it < UU; it++) {
        float bv = v0; int bi = t;
        if (v1 > bv) { bv = v1; bi = t + 1024; }
        #pragma unroll
        for (int o = 16; o > 0; o >>= 1) {
            float ov = __shfl_xor_sync(0xffffffffu, bv, o);
            int   oi = __shfl_xor_sync(0xffffffffu, bi, o);
            if (ov > bv || (ov == bv && oi < bi)) { bv = ov; bi = oi; }
        }
        if (lane == 0) { wv[wid] = bv; wi[wid] = bi; }
        __syncthreads();
        if (wid == 0) {
            bv = wv[lane]; bi = wi[lane];
            #pragma unroll
            for (int o = 16; o > 0; o >>= 1) {
                float ov = __shfl_xor_sync(0xffffffffu, bv, o);
                int   oi = __shfl_xor_sync(0xffffffffu, bi, o);
                if (ov > bv || (ov == bv && oi < bi)) { bv = ov; bi = oi; }
            }
            if (lane == 0) { g_top[bh * UU + it] = bi; winner = bi; }
        }
        __syncthreads();
        int win = winner;
        if (win == t) v0 = -3.4e38f;
        else if (win == t + 1024) v1 = -3.4e38f;
    }
}

// ---------------- 4) attention partials + v-mean partials ----------------
#define JC 128
#define ATTN_SMEM ((2560 + 128*65 + 128*64 + UU*128 + 256) * 4)
__global__ void __launch_bounds__(256) attn_part()
{
    const int jc = blockIdx.x, bh = blockIdx.y;
    const int j0 = jc * JC, t = threadIdx.x;
    extern __shared__ float sm[];
    float* qs = sm;
    float* ks = qs + 2560;
    float* vs = ks + 128 * 65;
    float* sc = vs + 128 * 64;
    float* vp = sc + UU * JC;

    for (int i = t; i < UU * DKK; i += 256) {
        int u = i >> 6, d = i & 63;
        qs[i] = g_q[((size_t)bh * SS + g_top[bh * UU + u]) * DKK + d];
    }
    for (int i = t; i < JC * DKK; i += 256) {
        int j = i >> 6, d = i & 63;
        ks[j * 65 + d] = g_k[((size_t)bh * SS + j0 + j) * DKK + d];
        vs[i]          = g_v[((size_t)bh * SS + j0 + j) * DKK + d];
    }
    __syncthreads();

    {
        const int d = t & 63, g = t >> 6;
        float a = 0.f;
        for (int j = g * 32; j < g * 32 + 32; j++) a += vs[j * DKK + d];
        vp[g * 64 + d] = a;
    }

    {
        const int jj = t & 31, ug = t >> 5;
        float acc[5][4];
        #pragma unroll
        for (int a = 0; a < 5; a++) { acc[a][0]=0.f; acc[a][1]=0.f; acc[a][2]=0.f; acc[a][3]=0.f; }
        for (int d = 0; d < DKK; d++) {
            float k0v = ks[jj*65+d], k1v = ks[(jj+32)*65+d];
            float k2v = ks[(jj+64)*65+d], k3v = ks[(jj+96)*65+d];
            #pragma unroll
            for (int a = 0; a < 5; a++) {
                float qv = qs[(ug * 5 + a) * DKK + d];
                acc[a][0] += qv*k0v; acc[a][1] += qv*k1v;
                acc[a][2] += qv*k2v; acc[a][3] += qv*k3v;
            }
        }
        #pragma unroll
        for (int a = 0; a < 5; a++) {
            int u = ug * 5 + a;
            sc[u*JC+jj] = acc[a][0]; sc[u*JC+jj+32] = acc[a][1];
            sc[u*JC+jj+64] = acc[a][2]; sc[u*JC+jj+96] = acc[a][3];
        }
    }
    __syncthreads();

    if (t < 64)
        g_vpart[((size_t)bh * NCH + jc) * DKK + t] = vp[t] + vp[t+64] + vp[t+128] + vp[t+192];

    {
        const int w = t >> 5, lid = t & 31;
        for (int u = w; u < UU; u += 8) {
            float a0 = sc[u*JC+lid], a1 = sc[u*JC+lid+32];
            float a2 = sc[u*JC+lid+64], a3 = sc[u*JC+lid+96];
            float mx = fmaxf(fmaxf(a0, a1), fmaxf(a2, a3));
            #pragma unroll
            for (int o = 16; o > 0; o >>= 1) mx = fmaxf(mx, __shfl_xor_sync(0xffffffffu, mx, o));
            float e0 = expf(a0-mx), e1 = expf(a1-mx), e2 = expf(a2-mx), e3 = expf(a3-mx);
            sc[u*JC+lid] = e0; sc[u*JC+lid+32] = e1; sc[u*JC+lid+64] = e2; sc[u*JC+lid+96] = e3;
            float s = e0 + e1 + e2 + e3;
            #pragma unroll
            for (int o = 16; o > 0; o >>= 1) s += __shfl_xor_sync(0xffffffffu, s, o);
            if (lid == 0) {
                g_pmax[(bh * NCH + jc) * UU + u] = mx;
                g_psum[(bh * NCH + jc) * UU + u] = s;
            }
        }
    }
    __syncthreads();

    {
        const int d2 = (t & 31) * 2, g8 = t >> 5;
        float acc[5][2];
        #pragma unroll
        for (int a = 0; a < 5; a++) { acc[a][0] = 0.f; acc[a][1] = 0.f; }
        for (int j = 0; j < JC; j++) {
            float v0 = vs[j*DKK+d2], v1 = vs[j*DKK+d2+1];
            #pragma unroll
            for (int a = 0; a < 5; a++) {
                float p = sc[(g8 * 5 + a) * JC + j];
                acc[a][0] += p * v0; acc[a][1] += p * v1;
            }
        }
        #pragma unroll
        for (int a = 0; a < 5; a++) {
            float* dst = g_po + ((size_t)(bh * NCH + jc) * UU + g8 * 5 + a) * DKK + d2;
            dst[0] = acc[a][0]; dst[1] = acc[a][1];
        }
    }
}

// ---------------- 5) merge partials + vmean finalize -> delta ------------
__global__ void attn_merge()
{
    const int bh = blockIdx.x, t = threadIdx.x;
    if (t < 64) {
        float a = 0.f;
        #pragma unroll
        for (int c = 0; c < NCH; c++) a += g_vpart[((size_t)bh * NCH + c) * DKK + t];
        g_vmean[bh * DKK + t] = a * (1.0f / (float)SS);
    }
    __syncthreads();
    const int w = t >> 5, lid = t & 31;
    for (int u = w; u < UU; u += 8) {
        float M = -3.4e38f;
        #pragma unroll
        for (int c = 0; c < NCH; c++) M = fmaxf(M, g_pmax[(bh * NCH + c) * UU + u]);
        float wc[NCH], T = 0.f;
        #pragma unroll
        for (int c = 0; c < NCH; c++) {
            wc[c] = expf(g_pmax[(bh * NCH + c) * UU + u] - M);
            T += g_psum[(bh * NCH + c) * UU + u] * wc[c];
        }
        float invT = 1.0f / T;
        for (int dd = lid; dd < DKK; dd += 32) {
            float acc = 0.f;
            #pragma unroll
            for (int c = 0; c < NCH; c++)
                acc += wc[c] * g_po[((size_t)(bh * NCH + c) * UU + u) * DKK + dd];
            g_delta[(bh * UU + u) * DKK + dd] = acc * invT - g_vmean[bh * DKK + dd];
        }
    }
}

// ---------------- 6) base row --------------------------------------------
__global__ void __launch_bounds__(1024) base_kernel(const float* __restrict__ fcw)
{
    const int b = blockIdx.y;
    const int n0 = blockIdx.x * 64;
    const int t = threadIdx.x;
    const int nl = t & 63, mg = t >> 6;
    __shared__ float cv[DM];
    __shared__ float part[16][64];
    if (t < DM) cv[t] = g_vmean[b * DM + t];
    __syncthreads();
    float acc = 0.f;
    #pragma unroll 8
    for (int m = mg * 64; m < mg * 64 + 64; m++)
        acc += cv[m] * fcw[(size_t)m * DM + n0 + nl];
    part[mg][nl] = acc;
    __syncthreads();
    if (t < 64) {
        float s = 0.f;
        #pragma unroll
        for (int g = 0; g < 16; g++) s += part[g][t];
        g_base[b * DM + n0 + t] = s;
    }
}

// ---------------- 7) pre = residual + base + fc_b ------------------------
__global__ void assemble_kernel(const float* __restrict__ hs, const float* __restrict__ fcb)
{
    size_t i = (size_t)blockIdx.x * 256 + threadIdx.x;
    int row = (int)(i / (DM / 4));
    int c4 = (int)(i % (DM / 4));
    int b = row >> 11;
    float4 r = ((const float4*)hs)[i];
    float4 bs = ((const float4*)g_base)[b * (DM / 4) + c4];
    float4 fb = ((const float4*)fcb)[c4];
    float4 o;
    o.x = r.x + bs.x + fb.x; o.y = r.y + bs.y + fb.y;
    o.z = r.z + bs.z + fb.z; o.w = r.w + bs.w + fb.w;
    ((float4*)g_pre)[i] = o;
}

// ---------------- 8) scatter delta-GEMM (grouped per bh) -----------------
__global__ void __launch_bounds__(256) scatter_kernel(const float* __restrict__ fcw)
{
    const int bh = blockIdx.y;
    const int n0 = blockIdx.x * 256;
    const int h = bh % HH, b = bh / HH;
    const int t = threadIdx.x;
    __shared__ float dl[UU * DKK];
    __shared__ int rows[UU];
    for (int i = t; i < UU * DKK; i += 256) dl[i] = g_delta[bh * UU * DKK + i];
    if (t < UU) rows[t] = g_top[bh * UU + t];
    __syncthreads();

    const int n = n0 + t;
    float acc[UU];
    #pragma unroll
    for (int u = 0; u < UU; u++) acc[u] = 0.f;
    const float* w = fcw + (size_t)(h * DKK) * DM + n;
    for (int d = 0; d < DKK; d++) {
        float wv = w[(size_t)d * DM];
        #pragma unroll
        for (int u = 0; u < UU; u++) acc[u] += dl[u * DKK + d] * wv;
    }
    #pragma unroll
    for (int u = 0; u < UU; u++)
        atomicAdd(&g_pre[((size_t)(b * SS + rows[u])) * DM + n], acc[u]);
}

// ---------------- 9) layernorm (single-load pass) ------------------------
__global__ void ln_kernel(const float* __restrict__ lnw, const float* __restrict__ lnb,
                          float* __restrict__ out)
{
    const int row = blockIdx.x, t = threadIdx.x;
    const float* x = g_pre + (size_t)row * DM;
    __shared__ float red[256];
    __shared__ float red2[256];
    float s = 0.f, s2 = 0.f;
    for (int i = t; i < DM; i += 256) {
        float v = x[i];
        s += v;
        s2 += v * v;
    }
    red[t] = s; red2[t] = s2;
    __syncthreads();
    for (int st = 128; st > 0; st >>= 1) {
        if (t < st) { red[t] += red[t + st]; red2[t] += red2[t + st]; }
        __syncthreads();
    }
    const float mu = red[0] * (1.0f / (float)DM);
    const float var = red2[0] * (1.0f / (float)DM) - mu * mu;
    const float rstd = rsqrtf(var + 1e-6f);
    for (int i = t; i < DM; i += 256)
        out[(size_t)row * DM + i] = (x[i] - mu) * rstd * lnw[i] + lnb[i];
}

// ---------------- launch --------------------------------------------------
extern "C" void kernel_launch(void* const* d_in, const int* in_sizes, int n_in,
                              void* d_out, int out_size)
{
    const float* hs  = (const float*)d_in[0];
    const float* wq  = (const float*)d_in[1];
    const float* wk  = (const float*)d_in[2];
    const float* wv  = (const float*)d_in[3];
    const float* fcw = (const float*)d_in[4];
    const float* fcb = (const float*)d_in[5];
    const float* lnw = (const float*)d_in[6];
    const float* lnb = (const float*)d_in[7];
    const int*   idx = (const int*)d_in[8];
    float* out = (float*)d_out;

    cudaFuncSetAttribute(qkv_mma, cudaFuncAttributeMaxDynamicSharedMemorySize, QSMEM);
    cudaFuncSetAttribute(attn_part, cudaFuncAttributeMaxDynamicSharedMemorySize, ATTN_SMEM);

    split2_hs<<<(int)((size_t)NR * DM / 2 / 256), 256>>>(hs);
    wtrans2<<<dim3(HDK / 32, DM / 32, 3), dim3(32, 8)>>>(wq, wk, wv);
    qkv_mma<<<dim3(8, 32, 3), 512, QSMEM>>>();
    sample_m_kernel<<<BH * 128, 512>>>(idx);
    topk_kernel<<<BH, 1024>>>();
    attn_part<<<dim3(NCH, BH), 256, ATTN_SMEM>>>();
    attn_merge<<<BH, 256>>>();
    base_kernel<<<dim3(DM / 64, BB), 1024>>>(fcw);
    assemble_kernel<<<(int)((size_t)NR * DM / 4 / 256), 256>>>(hs, fcb);
    scatter_kernel<<<dim3(DM / 256, BH), 256>>>(fcw);
    ln_kernel<<<NR, 256>>>(lnw, lnb, out);
}

// round 16
// speedup vs baseline: 1.0309x; 1.0309x over previous
#include <cuda_runtime.h>
#include <cuda_bf16.h>
#include <math.h>
#include <stdint.h>

#define BB 2
#define SS 2048
#define DM 1024
#define HH 16
#define DKK 64
#define HDK 1024
#define UU 40
#define SKK 40
#define NR (BB*SS)
#define BH (BB*HH)
#define NCH 16

// ---------------- device scratch ----------------
__device__ __align__(256) float g_q[(size_t)BH*SS*DKK];
__device__ __align__(256) float g_k[(size_t)BH*SS*DKK];
__device__ __align__(256) float g_v[(size_t)BH*SS*DKK];
__device__ __align__(256) float g_m[(size_t)BH*SS];
__device__ int   g_top[BH*UU];
__device__ __align__(256) float g_vmean[BH*DKK];
__device__ __align__(256) float g_vpart[BH*NCH*DKK];
__device__ __align__(256) float g_delta[BH*UU*DKK];
__device__ __align__(256) float g_base[BB*DM];
__device__ __align__(256) float g_pre[(size_t)NR*DM];
// packed bf16 planes
__device__ __align__(256) char g_pa0[10485760];
__device__ __align__(256) char g_pa1[10485760];
__device__ __align__(256) char g_pb0[7864320];
__device__ __align__(256) char g_pb1[7864320];
__device__ __align__(256) float g_pmax[BH*NCH*UU];
__device__ __align__(256) float g_psum[BH*NCH*UU];
__device__ __align__(256) float g_po[(size_t)BH*NCH*UU*DKK];

// ---------------- helpers ----------------
__device__ __forceinline__ uint32_t smem_u32(const void* p) {
    uint32_t a;
    asm("{ .reg .u64 t; cvta.to.shared.u64 t, %1; cvt.u32.u64 %0, t; }" : "=r"(a) : "l"(p));
    return a;
}
#define MB_INIT(mb, c)   asm volatile("mbarrier.init.shared.b64 [%0], %1;" :: "r"((uint32_t)(mb)), "r"((uint32_t)(c)) : "memory")
#define MB_EXPECT(mb, bytes) asm volatile("mbarrier.arrive.expect_tx.shared.b64 _, [%0], %1;" :: "r"((uint32_t)(mb)), "r"((uint32_t)(bytes)) : "memory")
#define MB_WAIT(mb, pa) do { \
    uint32_t _m = (uint32_t)(mb), _p = (uint32_t)(pa), _d; \
    asm volatile("{ .reg .pred p; mbarrier.try_wait.parity.acquire.cta.shared::cta.b64 p, [%1], %2; selp.b32 %0, 1, 0, p; }" : "=r"(_d) : "r"(_m), "r"(_p) : "memory"); \
    if (!_d) { asm volatile("{ .reg .pred P1;\nWL_%=: mbarrier.try_wait.parity.acquire.cta.shared::cta.b64 P1, [%0], %1, 0x989680;\n @P1 bra.uni WD_%=;\n bra.uni WL_%=;\nWD_%=: }" :: "r"(_m), "r"(_p) : "memory"); } } while (0)
#define BULK_G2S(dst, src, bytes, mb) \
    asm volatile("cp.async.bulk.shared::cluster.global.mbarrier::complete_tx::bytes [%0], [%1], %2, [%3];" \
        :: "r"((uint32_t)(dst)), "l"(src), "r"((uint32_t)(bytes)), "r"((uint32_t)(mb)) : "memory")
#define LDSM4(r0,r1,r2,r3,addr) \
    asm volatile("ldmatrix.sync.aligned.m8n8.x4.shared.b16 {%0,%1,%2,%3}, [%4];" \
        : "=r"(r0), "=r"(r1), "=r"(r2), "=r"(r3) : "r"(addr))
#define MMA16816(d0,d1,d2,d3,a0,a1,a2,a3,b0,b1) \
    asm volatile("mma.sync.aligned.m16n8k16.row.col.f32.bf16.bf16.f32 " \
        "{%0,%1,%2,%3}, {%4,%5,%6,%7}, {%8,%9}, {%0,%1,%2,%3};" \
        : "+f"(d0), "+f"(d1), "+f"(d2), "+f"(d3) \
        : "r"(a0), "r"(a1), "r"(a2), "r"(a3), "r"(b0), "r"(b1))

#define RSTR 80
#define AP 10240
#define BPQ 10240
#define STG (2*AP + 2*BPQ)
#define NSTG 2
#define QSMEM (NSTG*STG)
#define NCHK 32

// ---------------- 0a) split hidden_states -> packed 2-plane bf16 ---------
__global__ void split2_hs(const float* __restrict__ hs)
{
    size_t i = (size_t)blockIdx.x * 256 + threadIdx.x;
    int row = (int)(i >> 9);
    int k = (int)(i & 511) * 2;
    float2 x = ((const float2*)hs)[i];
    __nv_bfloat16 h0 = __float2bfloat16(x.x), h1 = __float2bfloat16(x.y);
    __nv_bfloat16 l0 = __float2bfloat16(x.x - __bfloat162float(h0));
    __nv_bfloat16 l1 = __float2bfloat16(x.y - __bfloat162float(h1));
    size_t off = ((size_t)((row >> 7) * 32 + (k >> 5))) * AP + (row & 127) * RSTR + (k & 31) * 2;
    *(__nv_bfloat162*)(g_pa0 + off) = __halves2bfloat162(h0, h1);
    *(__nv_bfloat162*)(g_pa1 + off) = __halves2bfloat162(l0, l1);
}

// ---------------- 0b) transpose W -> packed [n][k] 2-plane ---------------
__global__ void wtrans2(const float* __restrict__ wq, const float* __restrict__ wk,
                        const float* __restrict__ wv)
{
    int z = blockIdx.z;
    const float* __restrict__ W = (z == 0) ? wq : (z == 1) ? wk : wv;
    const float wsc = (z == 0) ? 0.125f : 1.0f;
    __shared__ float tile[32][33];
    int n0 = blockIdx.x * 32, k0 = blockIdx.y * 32;
    int tx = threadIdx.x, ty = threadIdx.y;
    #pragma unroll
    for (int i = 0; i < 4; i++)
        tile[ty + i*8][tx] = W[(size_t)(k0 + ty + i*8) * HDK + n0 + tx] * wsc;
    __syncthreads();
    #pragma unroll
    for (int i = 0; i < 4; i++) {
        float x = tile[tx][ty + i*8];
        __nv_bfloat16 h = __float2bfloat16(x);
        __nv_bfloat16 l = __float2bfloat16(x - __bfloat162float(h));
        int n = n0 + ty + i*8, k = k0 + tx;
        size_t off = (((size_t)(z * 8) + (n >> 7)) * 32 + (k >> 5)) * BPQ + (n & 127) * RSTR + (k & 31) * 2;
        *(__nv_bfloat16*)(g_pb0 + off) = h;
        *(__nv_bfloat16*)(g_pb1 + off) = l;
    }
}

// ---------------- shared tile body (R10-proven 128x128, 2 CTAs/SM) -------
__device__ __forceinline__ void qkv_tile(uint32_t sb, uint32_t mb0, int which, int rb, int nb)
{
    const int t = threadIdx.x, warp = t >> 5, lane = t & 31;
    const int row0 = rb * 128, n0 = nb * 128;
    const int wm = (warp >> 2) * 32, wn = (warp & 3) * 32;
    const int mi = lane >> 3, r8 = lane & 7;

    if (t == 0) { MB_INIT(mb0, 1); MB_INIT(mb0 + 8, 1); }
    __syncthreads();

    const char* sA0 = g_pa0 + (size_t)rb * 32 * AP;
    const char* sA1 = g_pa1 + (size_t)rb * 32 * AP;
    const char* sB0 = g_pb0 + (size_t)(which * 8 + nb) * 32 * BPQ;
    const char* sB1 = g_pb1 + (size_t)(which * 8 + nb) * 32 * BPQ;

    if (t == 0) {
        #pragma unroll
        for (int c = 0; c < NSTG; c++) {
            uint32_t mb = mb0 + c * 8;
            uint32_t dst = sb + c * STG;
            MB_EXPECT(mb, STG);
            BULK_G2S(dst,             sA0 + (size_t)c * AP,  AP,  mb);
            BULK_G2S(dst + AP,        sA1 + (size_t)c * AP,  AP,  mb);
            BULK_G2S(dst + 2*AP,      sB0 + (size_t)c * BPQ, BPQ, mb);
            BULK_G2S(dst + 2*AP+BPQ,  sB1 + (size_t)c * BPQ, BPQ, mb);
        }
    }

    float acc[2][4][4];
    #pragma unroll
    for (int i = 0; i < 2; i++)
        #pragma unroll
        for (int j = 0; j < 4; j++) {
            acc[i][j][0] = 0.f; acc[i][j][1] = 0.f; acc[i][j][2] = 0.f; acc[i][j][3] = 0.f;
        }

    for (int c = 0; c < NCHK; c++) {
        int s = c & 1;
        MB_WAIT(mb0 + s * 8, (c >> 1) & 1);

        uint32_t stA = sb + s * STG;
        uint32_t stB = stA + 2 * AP;

        #pragma unroll
        for (int si = 0; si < 2; si++) {
            uint32_t aoff = (uint32_t)((wm + (mi & 1) * 8 + r8) * RSTR + (si * 16 + (mi >> 1) * 8) * 2);
            uint32_t boff = (uint32_t)((wn + (mi >> 1) * 8 + r8) * RSTR + (si * 16 + (mi & 1) * 8) * 2);

            uint32_t a[2][4], bf[4][2];
            #pragma unroll
            for (int nt2 = 0; nt2 < 2; nt2++) {
                uint32_t ad = stB + boff + nt2 * 16 * RSTR;
                LDSM4(bf[nt2*2][0], bf[nt2*2][1], bf[nt2*2+1][0], bf[nt2*2+1][1], ad);
            }
            #pragma unroll
            for (int mt = 0; mt < 2; mt++) {
                uint32_t ad = stA + aoff + mt * 16 * RSTR;
                LDSM4(a[mt][0], a[mt][1], a[mt][2], a[mt][3], ad);
            }
            #pragma unroll
            for (int mt = 0; mt < 2; mt++)
                #pragma unroll
                for (int nt = 0; nt < 4; nt++)
                    MMA16816(acc[mt][nt][0], acc[mt][nt][1], acc[mt][nt][2], acc[mt][nt][3],
                             a[mt][0], a[mt][1], a[mt][2], a[mt][3], bf[nt][0], bf[nt][1]);
            #pragma unroll
            for (int mt = 0; mt < 2; mt++) {
                uint32_t ad = stA + AP + aoff + mt * 16 * RSTR;
                LDSM4(a[mt][0], a[mt][1], a[mt][2], a[mt][3], ad);
            }
            #pragma unroll
            for (int mt = 0; mt < 2; mt++)
                #pragma unroll
                for (int nt = 0; nt < 4; nt++)
                    MMA16816(acc[mt][nt][0], acc[mt][nt][1], acc[mt][nt][2], acc[mt][nt][3],
                             a[mt][0], a[mt][1], a[mt][2], a[mt][3], bf[nt][0], bf[nt][1]);
            #pragma unroll
            for (int nt2 = 0; nt2 < 2; nt2++) {
                uint32_t ad = stB + BPQ + boff + nt2 * 16 * RSTR;
                LDSM4(bf[nt2*2][0], bf[nt2*2][1], bf[nt2*2+1][0], bf[nt2*2+1][1], ad);
            }
            #pragma unroll
            for (int mt = 0; mt < 2; mt++) {
                uint32_t ad = stA + aoff + mt * 16 * RSTR;
                LDSM4(a[mt][0], a[mt][1], a[mt][2], a[mt][3], ad);
            }
            #pragma unroll
            for (int mt = 0; mt < 2; mt++)
                #pragma unroll
                for (int nt = 0; nt < 4; nt++)
                    MMA16816(acc[mt][nt][0], acc[mt][nt][1], acc[mt][nt][2], acc[mt][nt][3],
                             a[mt][0], a[mt][1], a[mt][2], a[mt][3], bf[nt][0], bf[nt][1]);
        }
        __syncthreads();
        if (t == 0 && c + NSTG < NCHK) {
            int cn = c + NSTG;
            uint32_t mb = mb0 + s * 8;
            uint32_t dst = sb + s * STG;
            MB_EXPECT(mb, STG);
            BULK_G2S(dst,            sA0 + (size_t)cn * AP,  AP,  mb);
            BULK_G2S(dst + AP,       sA1 + (size_t)cn * AP,  AP,  mb);
            BULK_G2S(dst + 2*AP,     sB0 + (size_t)cn * BPQ, BPQ, mb);
            BULK_G2S(dst + 2*AP+BPQ, sB1 + (size_t)cn * BPQ, BPQ, mb);
        }
    }

    float* __restrict__ O = (which == 0) ? g_q : (which == 1) ? g_k : g_v;
    const int gid = lane >> 2, tig = lane & 3;
    #pragma unroll
    for (int mt = 0; mt < 2; mt++) {
        int row = row0 + wm + mt * 16 + gid;
        int b = row >> 11, s = row & (SS - 1);
        int b8 = (row + 8) >> 11, s8 = (row + 8) & (SS - 1);
        #pragma unroll
        for (int nt = 0; nt < 4; nt++) {
            int col = n0 + wn + nt * 8 + tig * 2;
            int h = col >> 6, d0c = col & 63;
            float2 v0 = make_float2(acc[mt][nt][0], acc[mt][nt][1]);
            float2 v1 = make_float2(acc[mt][nt][2], acc[mt][nt][3]);
            *(float2*)&O[(((size_t)(b  * HH + h)) * SS + s ) * DKK + d0c] = v0;
            *(float2*)&O[(((size_t)(b8 * HH + h)) * SS + s8) * DKK + d0c] = v1;
        }
    }
}

// ---------------- 1) q,k GEMM --------------------------------------------
__global__ void __launch_bounds__(512, 2) qk_mma()
{
    extern __shared__ char smem[];
    __shared__ uint64_t mbars[NSTG];
    qkv_tile(smem_u32(smem), smem_u32(&mbars[0]), blockIdx.z, blockIdx.y, blockIdx.x);
}

// ---------------- 2) fused: v GEMM blocks + low-wavefront sample ---------
__device__ __forceinline__ void sample_warp(const int* __restrict__ idx, int bh, int l)
{
    const int lane = threadIdx.x & 31;
    const int jg = lane >> 3;
    const int sl = lane & 7;
    const float4* qr = (const float4*)(g_q + ((size_t)bh * SS + l) * DKK);
    float4 qa = qr[sl], qb = qr[sl + 8];
    const float* __restrict__ kbase = g_k + (size_t)bh * SS * DKK;
    const int* __restrict__ ip = idx + l * SKK;
    float mx = -3.4e38f, sm = 0.f;
    #pragma unroll
    for (int jt = 0; jt < SKK; jt += 4) {
        int kk = ip[jt + jg];
        const float4* kr = (const float4*)(kbase + (size_t)kk * DKK);
        float4 ka = kr[sl], kb = kr[sl + 8];
        float p = qa.x*ka.x + qa.y*ka.y + qa.z*ka.z + qa.w*ka.w
                + qb.x*kb.x + qb.y*kb.y + qb.z*kb.z + qb.w*kb.w;
        p += __shfl_xor_sync(0xffffffffu, p, 1);
        p += __shfl_xor_sync(0xffffffffu, p, 2);
        p += __shfl_xor_sync(0xffffffffu, p, 4);
        mx = fmaxf(mx, p);
        sm += p;
    }
    #pragma unroll
    for (int o = 8; o < 32; o <<= 1) {
        mx = fmaxf(mx, __shfl_xor_sync(0xffffffffu, mx, o));
        sm += __shfl_xor_sync(0xffffffffu, sm, o);
    }
    if (lane == 0) g_m[(size_t)bh * SS + l] = mx - sm * (1.0f / (float)SS);
}

__global__ void __launch_bounds__(512, 2) fused_v_sample(const int* __restrict__ idx)
{
    extern __shared__ char smem[];
    __shared__ uint64_t mbars[NSTG];
    if (blockIdx.x < 256) {
        qkv_tile(smem_u32(smem), smem_u32(&mbars[0]), 2, blockIdx.x >> 3, blockIdx.x & 7);
    } else {
        int sblk = blockIdx.x - 256;
        int bh = sblk >> 7;
        int l = ((sblk & 127) << 4) + (threadIdx.x >> 5);
        sample_warp(idx, bh, l);
    }
}

// ---------------- 3) top-40 ----------------------------------------------
__global__ void __launch_bounds__(1024) topk_kernel()
{
    const int bh = blockIdx.x, t = threadIdx.x;
    const int lane = t & 31, wid = t >> 5;
    __shared__ float wv[32];
    __shared__ int   wi[32];
    __shared__ int   winner;
    float v0 = g_m[(size_t)bh * SS + t];
    float v1 = g_m[(size_t)bh * SS + t + 1024];

    for (int it = 0; it < UU; it++) {
        float bv = v0; int bi = t;
        if (v1 > bv) { bv = v1; bi = t + 1024; }
        #pragma unroll
        for (int o = 16; o > 0; o >>= 1) {
            float ov = __shfl_xor_sync(0xffffffffu, bv, o);
            int   oi = __shfl_xor_sync(0xffffffffu, bi, o);
            if (ov > bv || (ov == bv && oi < bi)) { bv = ov; bi = oi; }
        }
        if (lane == 0) { wv[wid] = bv; wi[wid] = bi; }
        __syncthreads();
        if (wid == 0) {
            bv = wv[lane]; bi = wi[lane];
            #pragma unroll
            for (int o = 16; o > 0; o >>= 1) {
                float ov = __shfl_xor_sync(0xffffffffu, bv, o);
                int   oi = __shfl_xor_sync(0xffffffffu, bi, o);
                if (ov > bv || (ov == bv && oi < bi)) { bv = ov; bi = oi; }
            }
            if (lane == 0) { g_top[bh * UU + it] = bi; winner = bi; }
        }
        __syncthreads();
        int win = winner;
        if (win == t) v0 = -3.4e38f;
        else if (win == t + 1024) v1 = -3.4e38f;
    }
}

// ---------------- 4) attention partials + v-mean partials ----------------
#define JC 128
#define ATTN_SMEM ((2560 + 128*65 + 128*64 + UU*128 + 256) * 4)
__global__ void __launch_bounds__(256) attn_part()
{
    const int jc = blockIdx.x, bh = blockIdx.y;
    const int j0 = jc * JC, t = threadIdx.x;
    extern __shared__ float sm[];
    float* qs = sm;
    float* ks = qs + 2560;
    float* vs = ks + 128 * 65;
    float* sc = vs + 128 * 64;
    float* vp = sc + UU * JC;

    for (int i = t; i < UU * DKK; i += 256) {
        int u = i >> 6, d = i & 63;
        qs[i] = g_q[((size_t)bh * SS + g_top[bh * UU + u]) * DKK + d];
    }
    for (int i = t; i < JC * DKK; i += 256) {
        int j = i >> 6, d = i & 63;
        ks[j * 65 + d] = g_k[((size_t)bh * SS + j0 + j) * DKK + d];
        vs[i]          = g_v[((size_t)bh * SS + j0 + j) * DKK + d];
    }
    __syncthreads();

    {
        const int d = t & 63, g = t >> 6;
        float a = 0.f;
        for (int j = g * 32; j < g * 32 + 32; j++) a += vs[j * DKK + d];
        vp[g * 64 + d] = a;
    }

    {
        const int jj = t & 31, ug = t >> 5;
        float acc[5][4];
        #pragma unroll
        for (int a = 0; a < 5; a++) { acc[a][0]=0.f; acc[a][1]=0.f; acc[a][2]=0.f; acc[a][3]=0.f; }
        for (int d = 0; d < DKK; d++) {
            float k0v = ks[jj*65+d], k1v = ks[(jj+32)*65+d];
            float k2v = ks[(jj+64)*65+d], k3v = ks[(jj+96)*65+d];
            #pragma unroll
            for (int a = 0; a < 5; a++) {
                float qv = qs[(ug * 5 + a) * DKK + d];
                acc[a][0] += qv*k0v; acc[a][1] += qv*k1v;
                acc[a][2] += qv*k2v; acc[a][3] += qv*k3v;
            }
        }
        #pragma unroll
        for (int a = 0; a < 5; a++) {
            int u = ug * 5 + a;
            sc[u*JC+jj] = acc[a][0]; sc[u*JC+jj+32] = acc[a][1];
            sc[u*JC+jj+64] = acc[a][2]; sc[u*JC+jj+96] = acc[a][3];
        }
    }
    __syncthreads();

    if (t < 64)
        g_vpart[((size_t)bh * NCH + jc) * DKK + t] = vp[t] + vp[t+64] + vp[t+128] + vp[t+192];

    {
        const int w = t >> 5, lid = t & 31;
        for (int u = w; u < UU; u += 8) {
            float a0 = sc[u*JC+lid], a1 = sc[u*JC+lid+32];
            float a2 = sc[u*JC+lid+64], a3 = sc[u*JC+lid+96];
            float mx = fmaxf(fmaxf(a0, a1), fmaxf(a2, a3));
            #pragma unroll
            for (int o = 16; o > 0; o >>= 1) mx = fmaxf(mx, __shfl_xor_sync(0xffffffffu, mx, o));
            float e0 = expf(a0-mx), e1 = expf(a1-mx), e2 = expf(a2-mx), e3 = expf(a3-mx);
            sc[u*JC+lid] = e0; sc[u*JC+lid+32] = e1; sc[u*JC+lid+64] = e2; sc[u*JC+lid+96] = e3;
            float s = e0 + e1 + e2 + e3;
            #pragma unroll
            for (int o = 16; o > 0; o >>= 1) s += __shfl_xor_sync(0xffffffffu, s, o);
            if (lid == 0) {
                g_pmax[(bh * NCH + jc) * UU + u] = mx;
                g_psum[(bh * NCH + jc) * UU + u] = s;
            }
        }
    }
    __syncthreads();

    {
        const int d2 = (t & 31) * 2, g8 = t >> 5;
        float acc[5][2];
        #pragma unroll
        for (int a = 0; a < 5; a++) { acc[a][0] = 0.f; acc[a][1] = 0.f; }
        for (int j = 0; j < JC; j++) {
            float v0 = vs[j*DKK+d2], v1 = vs[j*DKK+d2+1];
            #pragma unroll
            for (int a = 0; a < 5; a++) {
                float p = sc[(g8 * 5 + a) * JC + j];
                acc[a][0] += p * v0; acc[a][1] += p * v1;
            }
        }
        #pragma unroll
        for (int a = 0; a < 5; a++) {
            float* dst = g_po + ((size_t)(bh * NCH + jc) * UU + g8 * 5 + a) * DKK + d2;
            dst[0] = acc[a][0]; dst[1] = acc[a][1];
        }
    }
}

// ---------------- 5) merge partials + vmean finalize -> delta ------------
__global__ void attn_merge()
{
    const int bh = blockIdx.x, t = threadIdx.x;
    if (t < 64) {
        float a = 0.f;
        #pragma unroll
        for (int c = 0; c < NCH; c++) a += g_vpart[((size_t)bh * NCH + c) * DKK + t];
        g_vmean[bh * DKK + t] = a * (1.0f / (float)SS);
    }
    __syncthreads();
    const int w = t >> 5, lid = t & 31;
    for (int u = w; u < UU; u += 8) {
        float M = -3.4e38f;
        #pragma unroll
        for (int c = 0; c < NCH; c++) M = fmaxf(M, g_pmax[(bh * NCH + c) * UU + u]);
        float wc[NCH], T = 0.f;
        #pragma unroll
        for (int c = 0; c < NCH; c++) {
            wc[c] = expf(g_pmax[(bh * NCH + c) * UU + u] - M);
            T += g_psum[(bh * NCH + c) * UU + u] * wc[c];
        }
        float invT = 1.0f / T;
        for (int dd = lid; dd < DKK; dd += 32) {
            float acc = 0.f;
            #pragma unroll
            for (int c = 0; c < NCH; c++)
                acc += wc[c] * g_po[((size_t)(bh * NCH + c) * UU + u) * DKK + dd];
            g_delta[(bh * UU + u) * DKK + dd] = acc * invT - g_vmean[bh * DKK + dd];
        }
    }
}

// ---------------- 6) base row --------------------------------------------
__global__ void __launch_bounds__(1024) base_kernel(const float* __restrict__ fcw)
{
    const int b = blockIdx.y;
    const int n0 = blockIdx.x * 64;
    const int t = threadIdx.x;
    const int nl = t & 63, mg = t >> 6;
    __shared__ float cv[DM];
    __shared__ float part[16][64];
    if (t < DM) cv[t] = g_vmean[b * DM + t];
    __syncthreads();
    float acc = 0.f;
    #pragma unroll 8
    for (int m = mg * 64; m < mg * 64 + 64; m++)
        acc += cv[m] * fcw[(size_t)m * DM + n0 + nl];
    part[mg][nl] = acc;
    __syncthreads();
    if (t < 64) {
        float s = 0.f;
        #pragma unroll
        for (int g = 0; g < 16; g++) s += part[g][t];
        g_base[b * DM + n0 + t] = s;
    }
}

// ---------------- 7) pre = residual + base + fc_b ------------------------
__global__ void assemble_kernel(const float* __restrict__ hs, const float* __restrict__ fcb)
{
    size_t i = (size_t)blockIdx.x * 256 + threadIdx.x;
    int row = (int)(i / (DM / 4));
    int c4 = (int)(i % (DM / 4));
    int b = row >> 11;
    float4 r = ((const float4*)hs)[i];
    float4 bs = ((const float4*)g_base)[b * (DM / 4) + c4];
    float4 fb = ((const float4*)fcb)[c4];
    float4 o;
    o.x = r.x + bs.x + fb.x; o.y = r.y + bs.y + fb.y;
    o.z = r.z + bs.z + fb.z; o.w = r.w + bs.w + fb.w;
    ((float4*)g_pre)[i] = o;
}

// ---------------- 8) scatter delta-GEMM (grouped per bh) -----------------
__global__ void __launch_bounds__(256) scatter_kernel(const float* __restrict__ fcw)
{
    const int bh = blockIdx.y;
    const int n0 = blockIdx.x * 256;
    const int h = bh % HH, b = bh / HH;
    const int t = threadIdx.x;
    __shared__ float dl[UU * DKK];
    __shared__ int rows[UU];
    for (int i = t; i < UU * DKK; i += 256) dl[i] = g_delta[bh * UU * DKK + i];
    if (t < UU) rows[t] = g_top[bh * UU + t];
    __syncthreads();

    const int n = n0 + t;
    float acc[UU];
    #pragma unroll
    for (int u = 0; u < UU; u++) acc[u] = 0.f;
    const float* w = fcw + (size_t)(h * DKK) * DM + n;
    for (int d = 0; d < DKK; d++) {
        float wv = w[(size_t)d * DM];
        #pragma unroll
        for (int u = 0; u < UU; u++) acc[u] += dl[u * DKK + d] * wv;
    }
    #pragma unroll
    for (int u = 0; u < UU; u++)
        atomicAdd(&g_pre[((size_t)(b * SS + rows[u])) * DM + n], acc[u]);
}

// ---------------- 9) layernorm (single-load pass) ------------------------
__global__ void ln_kernel(const float* __restrict__ lnw, const float* __restrict__ lnb,
                          float* __restrict__ out)
{
    const int row = blockIdx.x, t = threadIdx.x;
    const float* x = g_pre + (size_t)row * DM;
    __shared__ float red[256];
    __shared__ float red2[256];
    float s = 0.f, s2 = 0.f;
    for (int i = t; i < DM; i += 256) {
        float v = x[i];
        s += v;
        s2 += v * v;
    }
    red[t] = s; red2[t] = s2;
    __syncthreads();
    for (int st = 128; st > 0; st >>= 1) {
        if (t < st) { red[t] += red[t + st]; red2[t] += red2[t + st]; }
        __syncthreads();
    }
    const float mu = red[0] * (1.0f / (float)DM);
    const float var = red2[0] * (1.0f / (float)DM) - mu * mu;
    const float rstd = rsqrtf(var + 1e-6f);
    for (int i = t; i < DM; i += 256)
        out[(size_t)row * DM + i] = (x[i] - mu) * rstd * lnw[i] + lnb[i];
}

// ---------------- launch --------------------------------------------------
extern "C" void kernel_launch(void* const* d_in, const int* in_sizes, int n_in,
                              void* d_out, int out_size)
{
    const float* hs  = (const float*)d_in[0];
    const float* wq  = (const float*)d_in[1];
    const float* wk  = (const float*)d_in[2];
    const float* wv  = (const float*)d_in[3];
    const float* fcw = (const float*)d_in[4];
    const float* fcb = (const float*)d_in[5];
    const float* lnw = (const float*)d_in[6];
    const float* lnb = (const float*)d_in[7];
    const int*   idx = (const int*)d_in[8];
    float* out = (float*)d_out;

    cudaFuncSetAttribute(qk_mma, cudaFuncAttributeMaxDynamicSharedMemorySize, QSMEM);
    cudaFuncSetAttribute(fused_v_sample, cudaFuncAttributeMaxDynamicSharedMemorySize, QSMEM);
    cudaFuncSetAttribute(attn_part, cudaFuncAttributeMaxDynamicSharedMemorySize, ATTN_SMEM);

    split2_hs<<<(int)((size_t)NR * DM / 2 / 256), 256>>>(hs);
    wtrans2<<<dim3(HDK / 32, DM / 32, 3), dim3(32, 8)>>>(wq, wk, wv);
    qk_mma<<<dim3(8, 32, 2), 512, QSMEM>>>();
    fused_v_sample<<<256 + BH * 128, 512, QSMEM>>>(idx);
    topk_kernel<<<BH, 1024>>>();
    attn_part<<<dim3(NCH, BH), 256, ATTN_SMEM>>>();
    attn_merge<<<BH, 256>>>();
    base_kernel<<<dim3(DM / 64, BB), 1024>>>(fcw);
    assemble_kernel<<<(int)((size_t)NR * DM / 4 / 256), 256>>>(hs, fcb);
    scatter_kernel<<<dim3(DM / 256, BH), 256>>>(fcw);
    ln_kernel<<<NR, 256>>>(lnw, lnb, out);
}